// round 5
// baseline (speedup 1.0000x reference)
#include <cuda_runtime.h>
#include <math.h>
#include <stdint.h>

// ---------------------------------------------------------------------------
// Problem constants
// ---------------------------------------------------------------------------
#define S_LEN 1024
#define BATCH 4
#define EMB   1024
#define NH    16
#define HD    64
#define NTOK  (S_LEN * BATCH)     // 4096 tokens, token index t = s*BATCH + b
#define LN_EPS 1e-5f

// ---------------------------------------------------------------------------
// Scratch (device globals -- allocation-free kernel_launch requirement)
// ---------------------------------------------------------------------------
__device__ float g_h  [NTOK * EMB];        // 16 MB
__device__ float g_qkv[NTOK * 3 * EMB];    // 48 MB
__device__ float g_a  [NTOK * EMB];        // 16 MB
__device__ float g_x2 [NTOK * EMB];        // 16 MB
__device__ float g_m  [NTOK * 4 * EMB];    // 64 MB

// ---------------------------------------------------------------------------
// LayerNorm: one block per row (4096 rows of 1024), 256 threads, 1 float4 each
// ---------------------------------------------------------------------------
__global__ void __launch_bounds__(256) ln_kernel(
    const float* __restrict__ x, const float* __restrict__ gamma,
    const float* __restrict__ beta, float* __restrict__ out)
{
    const int row = blockIdx.x;
    const int t   = threadIdx.x;
    const float4* xr = reinterpret_cast<const float4*>(x + (size_t)row * EMB);
    float4 v = xr[t];

    float s  = v.x + v.y + v.z + v.w;
    float sq = v.x * v.x + v.y * v.y + v.z * v.z + v.w * v.w;
    #pragma unroll
    for (int m = 16; m > 0; m >>= 1) {
        s  += __shfl_xor_sync(0xffffffffu, s,  m);
        sq += __shfl_xor_sync(0xffffffffu, sq, m);
    }

    __shared__ float sh_s[8], sh_q[8];
    __shared__ float sh_mean, sh_rstd;
    const int warp = t >> 5, lane = t & 31;
    if (lane == 0) { sh_s[warp] = s; sh_q[warp] = sq; }
    __syncthreads();
    if (t == 0) {
        float ts = 0.f, tq = 0.f;
        #pragma unroll
        for (int i = 0; i < 8; i++) { ts += sh_s[i]; tq += sh_q[i]; }
        float mean = ts * (1.0f / EMB);
        float var  = tq * (1.0f / EMB) - mean * mean;
        sh_mean = mean;
        sh_rstd = rsqrtf(var + LN_EPS);
    }
    __syncthreads();
    const float mean = sh_mean, rstd = sh_rstd;

    float4 g4 = reinterpret_cast<const float4*>(gamma)[t];
    float4 b4 = reinterpret_cast<const float4*>(beta)[t];
    float4 o;
    o.x = (v.x - mean) * rstd * g4.x + b4.x;
    o.y = (v.y - mean) * rstd * g4.y + b4.y;
    o.z = (v.z - mean) * rstd * g4.z + b4.z;
    o.w = (v.w - mean) * rstd * g4.w + b4.w;
    reinterpret_cast<float4*>(out + (size_t)row * EMB)[t] = o;
}

// ---------------------------------------------------------------------------
// GELU (GPT-2 tanh approximation)
// ---------------------------------------------------------------------------
__device__ __forceinline__ float gelu_f(float x) {
    const float c = 0.7978845608028654f;   // sqrt(2/pi)
    float x3 = x * x * x;
    return 0.5f * x * (1.0f + tanhf(c * (x + 0.044715f * x3)));
}

// ---------------------------------------------------------------------------
// TF32 helpers
// ---------------------------------------------------------------------------
__device__ __forceinline__ uint32_t f2tf32(float x) {
    uint32_t u;
    asm("cvt.rna.tf32.f32 %0, %1;" : "=r"(u) : "f"(x));
    return u;
}

__device__ __forceinline__ void mma_tf32(
    float c[4], const uint32_t a[4], const uint32_t b[2])
{
    asm volatile(
        "mma.sync.aligned.m16n8k8.row.col.f32.tf32.tf32.f32 "
        "{%0,%1,%2,%3}, {%4,%5,%6,%7}, {%8,%9}, {%0,%1,%2,%3};\n"
        : "+f"(c[0]), "+f"(c[1]), "+f"(c[2]), "+f"(c[3])
        : "r"(a[0]), "r"(a[1]), "r"(a[2]), "r"(a[3]),
          "r"(b[0]), "r"(b[1]));
}

// ---------------------------------------------------------------------------
// TF32 tensor-core GEMM with FRAGMENT-PACKED smem layout.
//   C[M,N] = A[M,K] @ W[K,N] + bias; EPI 0:none 1:+res 2:gelu
// 128x128x32 block tile, 8 warps (2x4), 64x32 warp tile, m16n8k8.
// Smem stores tiles pre-packed in per-thread mma fragment order:
//   A: [mblk(8)][ks(4)][lane(32)][4xu32]  -> one LDS.128 per fragment
//   B: [nblk(16)][ks(4)][lane(32)][2xu32] -> one LDS.64  per fragment
// fp32->tf32 cvt happens once, at the packing store.
// ---------------------------------------------------------------------------
#define GASZ 4096                         // u32 per A buffer (16 KB)
#define GBSZ 4096                         // u32 per B buffer (16 KB)
#define GEMM_SMEM_BYTES ((2 * (GASZ + GBSZ)) * 4)   // 65536 B

template <int EPI>
__global__ void __launch_bounds__(256, 2) gemm_tf32(
    int M, int N, int K,
    const float* __restrict__ A, const float* __restrict__ W,
    const float* __restrict__ bias, const float* __restrict__ res,
    float* __restrict__ C)
{
    extern __shared__ uint32_t smem_u[];
    uint32_t* AsBase = smem_u;               // [2][GASZ]
    uint32_t* BsBase = smem_u + 2 * GASZ;    // [2][GBSZ]

    const int bm = blockIdx.y, bn = blockIdx.x;
    const int t    = threadIdx.x;
    const int warp = t >> 5, lane = t & 31;
    const int wm = warp >> 2;               // 0..1 : 64-row slab
    const int wn = warp & 3;                // 0..3 : 32-col slab
    const int g  = lane >> 2;               // 0..7
    const int q  = lane & 3;                // 0..3

    float acc[4][4][4];
    #pragma unroll
    for (int mi = 0; mi < 4; mi++)
        #pragma unroll
        for (int ni = 0; ni < 4; ni++)
            #pragma unroll
            for (int j = 0; j < 4; j++) acc[mi][ni][j] = 0.f;

    float4 abuf[4], bbuf[4];

    // ---- global loads (fp32), 4 float4 per thread per tile ----
    #define LOAD_A(k0)                                                         \
        {                                                                      \
            _Pragma("unroll")                                                  \
            for (int i = 0; i < 4; i++) {                                      \
                int idx = t + i * 256;                                         \
                int r = idx >> 3, c = (idx & 7) << 2;                          \
                abuf[i] = *reinterpret_cast<const float4*>(                    \
                    A + (size_t)(bm * 128 + r) * K + (k0) + c);                \
            }                                                                  \
        }
    #define LOAD_B(k0)                                                         \
        {                                                                      \
            _Pragma("unroll")                                                  \
            for (int i = 0; i < 4; i++) {                                      \
                int idx = t + i * 256;                                         \
                int r = idx >> 5, c = (idx & 31) << 2;                         \
                bbuf[i] = *reinterpret_cast<const float4*>(                    \
                    W + (size_t)((k0) + r) * N + bn * 128 + c);                \
            }                                                                  \
        }
    // ---- pack into fragment layout (tf32 cvt done here, once) ----
    // A element (m,k): mblk=m>>4, ks=k>>3, lane=(m&7)*4+(k&3),
    //                  j=((m>>3)&1) + 2*((k>>2)&1)
    // B element (k,n): nblk=n>>3, ks=k>>3, lane=(n&7)*4+(k&3), j=(k>>2)&1
    #define STORE_AB(bufsel)                                                   \
        {                                                                      \
            uint32_t* as = AsBase + (bufsel) * GASZ;                           \
            uint32_t* bs = BsBase + (bufsel) * GBSZ;                           \
            _Pragma("unroll")                                                  \
            for (int i = 0; i < 4; i++) {                                      \
                int idx  = t + i * 256;                                        \
                int r    = idx >> 3;            /* 0..127 (m) */               \
                int c4   = (idx & 7) << 2;      /* k base   */                 \
                int mblk = r >> 4, ga = r & 7, hir = (r >> 3) & 1;             \
                int ks   = c4 >> 3, hic = (c4 >> 2) & 1;                       \
                uint32_t* p = as + ((((mblk << 2) + ks) << 5) + (ga << 2)) * 4 \
                                 + hir + (hic << 1);                           \
                p[0]  = f2tf32(abuf[i].x);                                     \
                p[4]  = f2tf32(abuf[i].y);                                     \
                p[8]  = f2tf32(abuf[i].z);                                     \
                p[12] = f2tf32(abuf[i].w);                                     \
            }                                                                  \
            _Pragma("unroll")                                                  \
            for (int i = 0; i < 4; i++) {                                      \
                int idx  = t + i * 256;                                        \
                int r    = idx >> 5;            /* 0..31 (k) */                \
                int c4   = (idx & 31) << 2;     /* n base  */                  \
                int ksb  = r >> 3, qb = r & 3, jb = (r >> 2) & 1;              \
                int nblk = c4 >> 3, g0 = c4 & 7;                               \
                uint32_t* p = bs + ((((nblk << 2) + ksb) << 5) + qb) * 2 + jb  \
                                 + g0 * 8;                                     \
                p[0]  = f2tf32(bbuf[i].x);                                     \
                p[8]  = f2tf32(bbuf[i].y);                                     \
                p[16] = f2tf32(bbuf[i].z);                                     \
                p[24] = f2tf32(bbuf[i].w);                                     \
            }                                                                  \
        }

    LOAD_A(0); LOAD_B(0);
    STORE_AB(0);
    __syncthreads();

    int buf = 0;
    for (int k0 = 32; ; k0 += 32) {
        const bool more = (k0 < K);
        if (more) { LOAD_A(k0); LOAD_B(k0); }

        // ---- compute on current buffer: vector fragment loads ----
        {
            const uint32_t* aw = AsBase + buf * GASZ + wm * (16 * 128) + lane * 4;
            const uint32_t* bw = BsBase + buf * GBSZ + wn * (16 * 64)  + lane * 2;
            #pragma unroll
            for (int ks = 0; ks < 4; ks++) {
                uint32_t af[4][4], bf[4][2];
                #pragma unroll
                for (int mi = 0; mi < 4; mi++) {
                    uint4 va = *reinterpret_cast<const uint4*>(
                        aw + (mi * 4 + ks) * 128);
                    af[mi][0] = va.x; af[mi][1] = va.y;
                    af[mi][2] = va.z; af[mi][3] = va.w;
                }
                #pragma unroll
                for (int ni = 0; ni < 4; ni++) {
                    uint2 vb = *reinterpret_cast<const uint2*>(
                        bw + (ni * 4 + ks) * 64);
                    bf[ni][0] = vb.x; bf[ni][1] = vb.y;
                }
                #pragma unroll
                for (int mi = 0; mi < 4; mi++)
                    #pragma unroll
                    for (int ni = 0; ni < 4; ni++)
                        mma_tf32(acc[mi][ni], af[mi], bf[ni]);
            }
        }

        if (!more) break;
        STORE_AB(buf ^ 1);
        __syncthreads();
        buf ^= 1;
    }

    // ---- epilogue ----
    const int row_base = bm * 128 + wm * 64;
    const int col_base = bn * 128 + wn * 32;
    #pragma unroll
    for (int mi = 0; mi < 4; mi++) {
        #pragma unroll
        for (int ni = 0; ni < 4; ni++) {
            const int col = col_base + ni * 8 + 2 * q;
            const float b0 = bias[col], b1 = bias[col + 1];
            #pragma unroll
            for (int half = 0; half < 2; half++) {
                const int row = row_base + mi * 16 + g + half * 8;
                const size_t base = (size_t)row * N + col;
                float v0 = acc[mi][ni][half * 2 + 0] + b0;
                float v1 = acc[mi][ni][half * 2 + 1] + b1;
                if (EPI == 1) { v0 += res[base]; v1 += res[base + 1]; }
                if (EPI == 2) { v0 = gelu_f(v0); v1 = gelu_f(v1); }
                *reinterpret_cast<float2*>(C + base) = make_float2(v0, v1);
            }
        }
    }
    #undef LOAD_A
    #undef LOAD_B
    #undef STORE_AB
}

// ---------------------------------------------------------------------------
// Flash attention (fp32, no mask): one block per (b,h, 64-row q tile).
// ---------------------------------------------------------------------------
#define QS_STRIDE (HD + 1)
#define PS_STRIDE (64 + 1)
#define ATTN_SMEM_FLOATS (64 * QS_STRIDE + 64 * QS_STRIDE + \
                          64 * PS_STRIDE + 64 * HD)
#define ATTN_SMEM_BYTES  (ATTN_SMEM_FLOATS * 4)

__global__ void __launch_bounds__(256) attn_kernel(
    const float* __restrict__ qkv, float* __restrict__ out)
{
    extern __shared__ float sm[];
    float* Qs = sm;
    float* Ks = Qs + 64 * QS_STRIDE;
    float* Ps = Ks + 64 * QS_STRIDE;
    float* Vs = Ps + 64 * PS_STRIDE;

    const int bh = blockIdx.x;
    const int b  = bh / NH;
    const int h  = bh % NH;
    const int q0 = blockIdx.y * 64;

    const int t  = threadIdx.x;
    const int tr = t >> 4;
    const int tc = t & 15;
    const int r0 = tr * 4, c0 = tc * 4;

    #pragma unroll
    for (int i = 0; i < 4; i++) {
        const int idx = t + i * 256;
        const int r   = idx >> 4;
        const int c   = (idx & 15) << 2;
        const float4 v = *reinterpret_cast<const float4*>(
            qkv + (size_t)((q0 + r) * BATCH + b) * (3 * EMB) + h * HD + c);
        Qs[r * QS_STRIDE + c + 0] = v.x;
        Qs[r * QS_STRIDE + c + 1] = v.y;
        Qs[r * QS_STRIDE + c + 2] = v.z;
        Qs[r * QS_STRIDE + c + 3] = v.w;
    }

    float mrow[4], lrow[4], o[4][4];
    #pragma unroll
    for (int r = 0; r < 4; r++) {
        mrow[r] = -1e30f; lrow[r] = 0.f;
        #pragma unroll
        for (int c = 0; c < 4; c++) o[r][c] = 0.f;
    }

    for (int kt = 0; kt < S_LEN; kt += 64) {
        __syncthreads();
        #pragma unroll
        for (int i = 0; i < 4; i++) {
            const int idx = t + i * 256;
            const int r   = idx >> 4;
            const int c   = (idx & 15) << 2;
            const size_t base =
                (size_t)((kt + r) * BATCH + b) * (3 * EMB) + h * HD + c;
            const float4 kv = *reinterpret_cast<const float4*>(qkv + base + EMB);
            const float4 vv = *reinterpret_cast<const float4*>(qkv + base + 2 * EMB);
            Ks[r * QS_STRIDE + c + 0] = kv.x;
            Ks[r * QS_STRIDE + c + 1] = kv.y;
            Ks[r * QS_STRIDE + c + 2] = kv.z;
            Ks[r * QS_STRIDE + c + 3] = kv.w;
            *reinterpret_cast<float4*>(&Vs[r * HD + c]) = vv;
        }
        __syncthreads();

        float sacc[4][4];
        #pragma unroll
        for (int r = 0; r < 4; r++)
            #pragma unroll
            for (int c = 0; c < 4; c++) sacc[r][c] = 0.f;

        #pragma unroll 8
        for (int kk = 0; kk < HD; kk++) {
            float qv[4], kv[4];
            #pragma unroll
            for (int r = 0; r < 4; r++) qv[r] = Qs[(r0 + r) * QS_STRIDE + kk];
            #pragma unroll
            for (int c = 0; c < 4; c++) kv[c] = Ks[(c0 + c) * QS_STRIDE + kk];
            #pragma unroll
            for (int r = 0; r < 4; r++)
                #pragma unroll
                for (int c = 0; c < 4; c++)
                    sacc[r][c] = fmaf(qv[r], kv[c], sacc[r][c]);
        }

        #pragma unroll
        for (int r = 0; r < 4; r++) {
            float tmax = -1e30f;
            #pragma unroll
            for (int c = 0; c < 4; c++) {
                sacc[r][c] *= 0.125f;
                tmax = fmaxf(tmax, sacc[r][c]);
            }
            #pragma unroll
            for (int msk = 1; msk < 16; msk <<= 1)
                tmax = fmaxf(tmax, __shfl_xor_sync(0xffffffffu, tmax, msk));

            const float mnew  = fmaxf(mrow[r], tmax);
            const float alpha = __expf(mrow[r] - mnew);
            float tsum = 0.f;
            #pragma unroll
            for (int c = 0; c < 4; c++) {
                const float p = __expf(sacc[r][c] - mnew);
                Ps[(r0 + r) * PS_STRIDE + c0 + c] = p;
                tsum += p;
            }
            #pragma unroll
            for (int msk = 1; msk < 16; msk <<= 1)
                tsum += __shfl_xor_sync(0xffffffffu, tsum, msk);

            lrow[r] = lrow[r] * alpha + tsum;
            mrow[r] = mnew;
            #pragma unroll
            for (int c = 0; c < 4; c++) o[r][c] *= alpha;
        }
        __syncwarp();

        #pragma unroll 8
        for (int j = 0; j < 64; j++) {
            float pv[4], vv[4];
            #pragma unroll
            for (int r = 0; r < 4; r++) pv[r] = Ps[(r0 + r) * PS_STRIDE + j];
            #pragma unroll
            for (int c = 0; c < 4; c++) vv[c] = Vs[j * HD + c0 + c];
            #pragma unroll
            for (int r = 0; r < 4; r++)
                #pragma unroll
                for (int c = 0; c < 4; c++)
                    o[r][c] = fmaf(pv[r], vv[c], o[r][c]);
        }
    }

    #pragma unroll
    for (int r = 0; r < 4; r++) {
        const float inv = 1.0f / lrow[r];
        const int s = q0 + r0 + r;
        float* dst = out + (size_t)(s * BATCH + b) * EMB + h * HD + c0;
        *reinterpret_cast<float4*>(dst) =
            make_float4(o[r][0] * inv, o[r][1] * inv, o[r][2] * inv, o[r][3] * inv);
    }
}

// ---------------------------------------------------------------------------
// Launch
// ---------------------------------------------------------------------------
extern "C" void kernel_launch(void* const* d_in, const int* in_sizes, int n_in,
                              void* d_out, int out_size)
{
    const float* x      = (const float*)d_in[0];
    const float* ln1_g  = (const float*)d_in[1];
    const float* ln1_b  = (const float*)d_in[2];
    const float* w_attn = (const float*)d_in[3];
    const float* b_attn = (const float*)d_in[4];
    const float* w_proj = (const float*)d_in[5];
    const float* b_proj = (const float*)d_in[6];
    const float* ln2_g  = (const float*)d_in[7];
    const float* ln2_b  = (const float*)d_in[8];
    const float* w_fc   = (const float*)d_in[9];
    const float* b_fc   = (const float*)d_in[10];
    const float* w_out  = (const float*)d_in[11];
    const float* b_out  = (const float*)d_in[12];
    float* out = (float*)d_out;

    void *p_h, *p_qkv, *p_a, *p_x2, *p_m;
    cudaGetSymbolAddress(&p_h,   g_h);
    cudaGetSymbolAddress(&p_qkv, g_qkv);
    cudaGetSymbolAddress(&p_a,   g_a);
    cudaGetSymbolAddress(&p_x2,  g_x2);
    cudaGetSymbolAddress(&p_m,   g_m);
    float* h   = (float*)p_h;
    float* qkv = (float*)p_qkv;
    float* a   = (float*)p_a;
    float* x2  = (float*)p_x2;
    float* mm  = (float*)p_m;

    cudaFuncSetAttribute(attn_kernel,
                         cudaFuncAttributeMaxDynamicSharedMemorySize,
                         ATTN_SMEM_BYTES);
    cudaFuncSetAttribute(gemm_tf32<0>,
                         cudaFuncAttributeMaxDynamicSharedMemorySize,
                         GEMM_SMEM_BYTES);
    cudaFuncSetAttribute(gemm_tf32<1>,
                         cudaFuncAttributeMaxDynamicSharedMemorySize,
                         GEMM_SMEM_BYTES);
    cudaFuncSetAttribute(gemm_tf32<2>,
                         cudaFuncAttributeMaxDynamicSharedMemorySize,
                         GEMM_SMEM_BYTES);

    // 1. ln1
    ln_kernel<<<NTOK, 256>>>(x, ln1_g, ln1_b, h);
    // 2. qkv = h @ w_attn + b_attn            [4096, 3072]
    gemm_tf32<0><<<dim3(3 * EMB / 128, NTOK / 128), 256, GEMM_SMEM_BYTES>>>(
        NTOK, 3 * EMB, EMB, h, w_attn, b_attn, nullptr, qkv);
    // 3. attention -> a (merged heads, token layout)
    attn_kernel<<<dim3(BATCH * NH, S_LEN / 64), 256, ATTN_SMEM_BYTES>>>(qkv, a);
    // 4. x2 = x + a @ w_proj + b_proj
    gemm_tf32<1><<<dim3(EMB / 128, NTOK / 128), 256, GEMM_SMEM_BYTES>>>(
        NTOK, EMB, EMB, a, w_proj, b_proj, x, x2);
    // 5. ln2
    ln_kernel<<<NTOK, 256>>>(x2, ln2_g, ln2_b, h);
    // 6. m = gelu(h @ w_fc + b_fc)            [4096, 4096]
    gemm_tf32<2><<<dim3(4 * EMB / 128, NTOK / 128), 256, GEMM_SMEM_BYTES>>>(
        NTOK, 4 * EMB, EMB, h, w_fc, b_fc, nullptr, mm);
    // 7. out = x2 + m @ w_out + b_out
    gemm_tf32<1><<<dim3(EMB / 128, NTOK / 128), 256, GEMM_SMEM_BYTES>>>(
        NTOK, EMB, 4 * EMB, mm, w_out, b_out, x2, out);
}

// round 6
// speedup vs baseline: 2.5151x; 2.5151x over previous
#include <cuda_runtime.h>
#include <math.h>
#include <stdint.h>

// ---------------------------------------------------------------------------
// Problem constants
// ---------------------------------------------------------------------------
#define S_LEN 1024
#define BATCH 4
#define EMB   1024
#define NH    16
#define HD    64
#define NTOK  (S_LEN * BATCH)     // 4096 tokens, token index t = s*BATCH + b
#define LN_EPS 1e-5f

// ---------------------------------------------------------------------------
// Scratch (device globals -- allocation-free kernel_launch requirement)
// ---------------------------------------------------------------------------
__device__ float g_h  [NTOK * EMB];          // 16 MB (ln output, tf32-rounded)
__device__ float g_qkv[NTOK * 3 * EMB];      // 48 MB
__device__ float g_a  [NTOK * EMB];          // 16 MB (attn out, tf32-rounded)
__device__ float g_x2 [NTOK * EMB];          // 16 MB
__device__ float g_m  [NTOK * 4 * EMB];      // 64 MB (gelu out, tf32-rounded)
__device__ float g_wt [12 * EMB * EMB];      // 48 MB (tf32-rounded weights)
// g_wt offsets (floats): w_attn 0, w_proj 3*E*E, w_fc 4*E*E, w_out 8*E*E

// ---------------------------------------------------------------------------
// TF32 helpers
// ---------------------------------------------------------------------------
__device__ __forceinline__ uint32_t f2tf32(float x) {
    uint32_t u;
    asm("cvt.rna.tf32.f32 %0, %1;" : "=r"(u) : "f"(x));
    return u;
}
__device__ __forceinline__ float tf32r(float x) {   // round-to-nearest tf32 value
    return __uint_as_float(f2tf32(x));
}

__device__ __forceinline__ void mma_tf32(
    float c[4], const uint32_t a[4], const uint32_t b[2])
{
    asm volatile(
        "mma.sync.aligned.m16n8k8.row.col.f32.tf32.tf32.f32 "
        "{%0,%1,%2,%3}, {%4,%5,%6,%7}, {%8,%9}, {%0,%1,%2,%3};\n"
        : "+f"(c[0]), "+f"(c[1]), "+f"(c[2]), "+f"(c[3])
        : "r"(a[0]), "r"(a[1]), "r"(a[2]), "r"(a[3]),
          "r"(b[0]), "r"(b[1]));
}

// cp.async helpers
__device__ __forceinline__ void cp_async16(void* smem_ptr, const void* gptr) {
    uint32_t s = (uint32_t)__cvta_generic_to_shared(smem_ptr);
    asm volatile("cp.async.cg.shared.global [%0], [%1], 16;\n"
                 :: "r"(s), "l"(gptr));
}
__device__ __forceinline__ void cp_commit() {
    asm volatile("cp.async.commit_group;\n");
}
template <int N>
__device__ __forceinline__ void cp_wait() {
    asm volatile("cp.async.wait_group %0;\n" :: "n"(N));
}

// ---------------------------------------------------------------------------
// Weight pre-rounding: dst = tf32_round(src), vectorized float4
// ---------------------------------------------------------------------------
__global__ void __launch_bounds__(256) round_tf32_kernel(
    const float* __restrict__ src, float* __restrict__ dst, int n4)
{
    int i = blockIdx.x * 256 + threadIdx.x;
    if (i < n4) {
        float4 v = reinterpret_cast<const float4*>(src)[i];
        v.x = tf32r(v.x); v.y = tf32r(v.y); v.z = tf32r(v.z); v.w = tf32r(v.w);
        reinterpret_cast<float4*>(dst)[i] = v;
    }
}

// ---------------------------------------------------------------------------
// LayerNorm (output tf32-rounded: it only ever feeds GEMM A-operands)
// ---------------------------------------------------------------------------
__global__ void __launch_bounds__(256) ln_kernel(
    const float* __restrict__ x, const float* __restrict__ gamma,
    const float* __restrict__ beta, float* __restrict__ out)
{
    const int row = blockIdx.x;
    const int t   = threadIdx.x;
    const float4* xr = reinterpret_cast<const float4*>(x + (size_t)row * EMB);
    float4 v = xr[t];

    float s  = v.x + v.y + v.z + v.w;
    float sq = v.x * v.x + v.y * v.y + v.z * v.z + v.w * v.w;
    #pragma unroll
    for (int m = 16; m > 0; m >>= 1) {
        s  += __shfl_xor_sync(0xffffffffu, s,  m);
        sq += __shfl_xor_sync(0xffffffffu, sq, m);
    }

    __shared__ float sh_s[8], sh_q[8];
    __shared__ float sh_mean, sh_rstd;
    const int warp = t >> 5, lane = t & 31;
    if (lane == 0) { sh_s[warp] = s; sh_q[warp] = sq; }
    __syncthreads();
    if (t == 0) {
        float ts = 0.f, tq = 0.f;
        #pragma unroll
        for (int i = 0; i < 8; i++) { ts += sh_s[i]; tq += sh_q[i]; }
        float mean = ts * (1.0f / EMB);
        float var  = tq * (1.0f / EMB) - mean * mean;
        sh_mean = mean;
        sh_rstd = rsqrtf(var + LN_EPS);
    }
    __syncthreads();
    const float mean = sh_mean, rstd = sh_rstd;

    float4 g4 = reinterpret_cast<const float4*>(gamma)[t];
    float4 b4 = reinterpret_cast<const float4*>(beta)[t];
    float4 o;
    o.x = tf32r((v.x - mean) * rstd * g4.x + b4.x);
    o.y = tf32r((v.y - mean) * rstd * g4.y + b4.y);
    o.z = tf32r((v.z - mean) * rstd * g4.z + b4.z);
    o.w = tf32r((v.w - mean) * rstd * g4.w + b4.w);
    reinterpret_cast<float4*>(out + (size_t)row * EMB)[t] = o;
}

// ---------------------------------------------------------------------------
// GELU (GPT-2 tanh approximation)
// ---------------------------------------------------------------------------
__device__ __forceinline__ float gelu_f(float x) {
    const float c = 0.7978845608028654f;   // sqrt(2/pi)
    float x3 = x * x * x;
    return 0.5f * x * (1.0f + tanhf(c * (x + 0.044715f * x3)));
}

// ---------------------------------------------------------------------------
// TF32 tensor-core GEMM, cp.async 3-stage pipeline.
//   C[M,N] = A[M,K] @ W[K,N] + bias; EPI 0:none 1:+res 2:gelu(+tf32 round)
// Inputs A and W must already hold tf32-representable values (pre-rounded),
// so raw bits feed the mma with zero conversion error.
// 128x128x32 block tile, 8 warps (2x4), 64x32 warp tile, m16n8k8.
// Smem (per stage): A [128][36] u32 (pad 36), B [32][136] u32 (pad 136) --
// the round-4-verified conflict-free layout.
// ---------------------------------------------------------------------------
#define GAST 36
#define GBST 136
#define GA_STG (128 * GAST)               // 4608 u32
#define GB_STG (32 * GBST)                // 4352 u32
#define G_STG  (GA_STG + GB_STG)          // 8960 u32 = 35840 B
#define NSTAGE 3
#define GEMM_SMEM_BYTES (NSTAGE * G_STG * 4)   // 107520 B

template <int EPI>
__global__ void __launch_bounds__(256, 2) gemm_tf32(
    int M, int N, int K,
    const float* __restrict__ A, const float* __restrict__ W,
    const float* __restrict__ bias, const float* __restrict__ res,
    float* __restrict__ C)
{
    extern __shared__ uint32_t smem_u[];

    const int bm = blockIdx.y, bn = blockIdx.x;
    const int t    = threadIdx.x;
    const int warp = t >> 5, lane = t & 31;
    const int wm = warp >> 2;               // 0..1 : 64-row slab
    const int wn = warp & 3;                // 0..3 : 32-col slab
    const int g  = lane >> 5 ? 0 : (lane >> 2);   // 0..7
    const int q  = lane & 3;                // 0..3

    // ---- staging geometry (per thread, 4 x 16B for A and for B) ----
    const int arow0 = t >> 3;               // +i*32
    const int ac    = (t & 7) << 2;
    const int brow0 = t >> 5;               // +i*8
    const int bc    = (t & 31) << 2;
    const float* aSrc = A + (size_t)(bm * 128 + arow0) * K + ac;
    const float* bSrc = W + (size_t)brow0 * N + bn * 128 + bc;
    const int aDst = arow0 * GAST + ac;     // +i*32*GAST
    const int bDst = brow0 * GBST + bc;     // +i*8*GBST

    float acc[4][4][4];
    #pragma unroll
    for (int mi = 0; mi < 4; mi++)
        #pragma unroll
        for (int ni = 0; ni < 4; ni++)
            #pragma unroll
            for (int j = 0; j < 4; j++) acc[mi][ni][j] = 0.f;

    #define ISSUE(stg, kt)                                                     \
        {                                                                      \
            uint32_t* as = smem_u + (stg) * G_STG;                             \
            uint32_t* bs = as + GA_STG;                                        \
            _Pragma("unroll")                                                  \
            for (int i = 0; i < 4; i++)                                        \
                cp_async16(as + aDst + i * (32 * GAST),                        \
                           aSrc + (size_t)(kt) * 32 + (size_t)i * 32 * K);     \
            _Pragma("unroll")                                                  \
            for (int i = 0; i < 4; i++)                                        \
                cp_async16(bs + bDst + i * (8 * GBST),                         \
                           bSrc + ((size_t)(kt) * 32 + i * 8) * N);            \
        }

    const int ntiles = K / 32;              // >= 32 always
    ISSUE(0, 0); cp_commit();
    ISSUE(1, 1); cp_commit();

    int buf = 0;
    for (int kt = 0; kt < ntiles; kt++) {
        cp_wait<1>();
        __syncthreads();

        if (kt + 2 < ntiles) {
            int nstg = buf + 2; if (nstg >= NSTAGE) nstg -= NSTAGE;
            ISSUE(nstg, kt + 2);
        }
        cp_commit();

        // ---- compute on stage `buf` (round-4 layout, conflict-free) ----
        {
            const uint32_t* as = smem_u + buf * G_STG + (wm * 64 + g) * GAST;
            const uint32_t* bs = smem_u + buf * G_STG + GA_STG + wn * 32 + g;
            #pragma unroll
            for (int ks = 0; ks < 4; ks++) {
                const int kk = ks * 8;
                uint32_t af[4][4], bf[4][2];
                #pragma unroll
                for (int mi = 0; mi < 4; mi++) {
                    const uint32_t* p = as + mi * 16 * GAST + kk + q;
                    af[mi][0] = p[0];
                    af[mi][1] = p[8 * GAST];
                    af[mi][2] = p[4];
                    af[mi][3] = p[8 * GAST + 4];
                }
                #pragma unroll
                for (int ni = 0; ni < 4; ni++) {
                    const uint32_t* p = bs + (kk + q) * GBST + ni * 8;
                    bf[ni][0] = p[0];
                    bf[ni][1] = p[4 * GBST];
                }
                #pragma unroll
                for (int mi = 0; mi < 4; mi++)
                    #pragma unroll
                    for (int ni = 0; ni < 4; ni++)
                        mma_tf32(acc[mi][ni], af[mi], bf[ni]);
            }
        }

        buf++; if (buf == NSTAGE) buf = 0;
    }
    #undef ISSUE

    // ---- epilogue ----
    const int row_base = bm * 128 + wm * 64;
    const int col_base = bn * 128 + wn * 32;
    #pragma unroll
    for (int mi = 0; mi < 4; mi++) {
        #pragma unroll
        for (int ni = 0; ni < 4; ni++) {
            const int col = col_base + ni * 8 + 2 * q;
            const float b0 = bias[col], b1 = bias[col + 1];
            #pragma unroll
            for (int half = 0; half < 2; half++) {
                const int row = row_base + mi * 16 + g + half * 8;
                const size_t base = (size_t)row * N + col;
                float v0 = acc[mi][ni][half * 2 + 0] + b0;
                float v1 = acc[mi][ni][half * 2 + 1] + b1;
                if (EPI == 1) { v0 += res[base]; v1 += res[base + 1]; }
                if (EPI == 2) {
                    v0 = tf32r(gelu_f(v0));   // feeds next GEMM's A operand
                    v1 = tf32r(gelu_f(v1));
                }
                *reinterpret_cast<float2*>(C + base) = make_float2(v0, v1);
            }
        }
    }
}

// ---------------------------------------------------------------------------
// Flash attention (fp32, no mask): one block per (b,h, 64-row q tile).
// Output tf32-rounded (feeds proj GEMM A operand).
// ---------------------------------------------------------------------------
#define QS_STRIDE (HD + 1)
#define PS_STRIDE (64 + 1)
#define ATTN_SMEM_FLOATS (64 * QS_STRIDE + 64 * QS_STRIDE + \
                          64 * PS_STRIDE + 64 * HD)
#define ATTN_SMEM_BYTES  (ATTN_SMEM_FLOATS * 4)

__global__ void __launch_bounds__(256) attn_kernel(
    const float* __restrict__ qkv, float* __restrict__ out)
{
    extern __shared__ float sm[];
    float* Qs = sm;
    float* Ks = Qs + 64 * QS_STRIDE;
    float* Ps = Ks + 64 * QS_STRIDE;
    float* Vs = Ps + 64 * PS_STRIDE;

    const int bh = blockIdx.x;
    const int b  = bh / NH;
    const int h  = bh % NH;
    const int q0 = blockIdx.y * 64;

    const int t  = threadIdx.x;
    const int tr = t >> 4;
    const int tc = t & 15;
    const int r0 = tr * 4, c0 = tc * 4;

    #pragma unroll
    for (int i = 0; i < 4; i++) {
        const int idx = t + i * 256;
        const int r   = idx >> 4;
        const int c   = (idx & 15) << 2;
        const float4 v = *reinterpret_cast<const float4*>(
            qkv + (size_t)((q0 + r) * BATCH + b) * (3 * EMB) + h * HD + c);
        Qs[r * QS_STRIDE + c + 0] = v.x;
        Qs[r * QS_STRIDE + c + 1] = v.y;
        Qs[r * QS_STRIDE + c + 2] = v.z;
        Qs[r * QS_STRIDE + c + 3] = v.w;
    }

    float mrow[4], lrow[4], o[4][4];
    #pragma unroll
    for (int r = 0; r < 4; r++) {
        mrow[r] = -1e30f; lrow[r] = 0.f;
        #pragma unroll
        for (int c = 0; c < 4; c++) o[r][c] = 0.f;
    }

    for (int kt = 0; kt < S_LEN; kt += 64) {
        __syncthreads();
        #pragma unroll
        for (int i = 0; i < 4; i++) {
            const int idx = t + i * 256;
            const int r   = idx >> 4;
            const int c   = (idx & 15) << 2;
            const size_t base =
                (size_t)((kt + r) * BATCH + b) * (3 * EMB) + h * HD + c;
            const float4 kv = *reinterpret_cast<const float4*>(qkv + base + EMB);
            const float4 vv = *reinterpret_cast<const float4*>(qkv + base + 2 * EMB);
            Ks[r * QS_STRIDE + c + 0] = kv.x;
            Ks[r * QS_STRIDE + c + 1] = kv.y;
            Ks[r * QS_STRIDE + c + 2] = kv.z;
            Ks[r * QS_STRIDE + c + 3] = kv.w;
            *reinterpret_cast<float4*>(&Vs[r * HD + c]) = vv;
        }
        __syncthreads();

        float sacc[4][4];
        #pragma unroll
        for (int r = 0; r < 4; r++)
            #pragma unroll
            for (int c = 0; c < 4; c++) sacc[r][c] = 0.f;

        #pragma unroll 8
        for (int kk = 0; kk < HD; kk++) {
            float qv[4], kv[4];
            #pragma unroll
            for (int r = 0; r < 4; r++) qv[r] = Qs[(r0 + r) * QS_STRIDE + kk];
            #pragma unroll
            for (int c = 0; c < 4; c++) kv[c] = Ks[(c0 + c) * QS_STRIDE + kk];
            #pragma unroll
            for (int r = 0; r < 4; r++)
                #pragma unroll
                for (int c = 0; c < 4; c++)
                    sacc[r][c] = fmaf(qv[r], kv[c], sacc[r][c]);
        }

        #pragma unroll
        for (int r = 0; r < 4; r++) {
            float tmax = -1e30f;
            #pragma unroll
            for (int c = 0; c < 4; c++) {
                sacc[r][c] *= 0.125f;
                tmax = fmaxf(tmax, sacc[r][c]);
            }
            #pragma unroll
            for (int msk = 1; msk < 16; msk <<= 1)
                tmax = fmaxf(tmax, __shfl_xor_sync(0xffffffffu, tmax, msk));

            const float mnew  = fmaxf(mrow[r], tmax);
            const float alpha = __expf(mrow[r] - mnew);
            float tsum = 0.f;
            #pragma unroll
            for (int c = 0; c < 4; c++) {
                const float p = __expf(sacc[r][c] - mnew);
                Ps[(r0 + r) * PS_STRIDE + c0 + c] = p;
                tsum += p;
            }
            #pragma unroll
            for (int msk = 1; msk < 16; msk <<= 1)
                tsum += __shfl_xor_sync(0xffffffffu, tsum, msk);

            lrow[r] = lrow[r] * alpha + tsum;
            mrow[r] = mnew;
            #pragma unroll
            for (int c = 0; c < 4; c++) o[r][c] *= alpha;
        }
        __syncwarp();

        #pragma unroll 8
        for (int j = 0; j < 64; j++) {
            float pv[4], vv[4];
            #pragma unroll
            for (int r = 0; r < 4; r++) pv[r] = Ps[(r0 + r) * PS_STRIDE + j];
            #pragma unroll
            for (int c = 0; c < 4; c++) vv[c] = Vs[j * HD + c0 + c];
            #pragma unroll
            for (int r = 0; r < 4; r++)
                #pragma unroll
                for (int c = 0; c < 4; c++)
                    o[r][c] = fmaf(pv[r], vv[c], o[r][c]);
        }
    }

    #pragma unroll
    for (int r = 0; r < 4; r++) {
        const float inv = 1.0f / lrow[r];
        const int s = q0 + r0 + r;
        float* dst = out + (size_t)(s * BATCH + b) * EMB + h * HD + c0;
        *reinterpret_cast<float4*>(dst) =
            make_float4(tf32r(o[r][0] * inv), tf32r(o[r][1] * inv),
                        tf32r(o[r][2] * inv), tf32r(o[r][3] * inv));
    }
}

// ---------------------------------------------------------------------------
// Launch
// ---------------------------------------------------------------------------
extern "C" void kernel_launch(void* const* d_in, const int* in_sizes, int n_in,
                              void* d_out, int out_size)
{
    const float* x      = (const float*)d_in[0];
    const float* ln1_g  = (const float*)d_in[1];
    const float* ln1_b  = (const float*)d_in[2];
    const float* w_attn = (const float*)d_in[3];
    const float* b_attn = (const float*)d_in[4];
    const float* w_proj = (const float*)d_in[5];
    const float* b_proj = (const float*)d_in[6];
    const float* ln2_g  = (const float*)d_in[7];
    const float* ln2_b  = (const float*)d_in[8];
    const float* w_fc   = (const float*)d_in[9];
    const float* b_fc   = (const float*)d_in[10];
    const float* w_out  = (const float*)d_in[11];
    const float* b_out  = (const float*)d_in[12];
    float* out = (float*)d_out;

    void *p_h, *p_qkv, *p_a, *p_x2, *p_m, *p_wt;
    cudaGetSymbolAddress(&p_h,   g_h);
    cudaGetSymbolAddress(&p_qkv, g_qkv);
    cudaGetSymbolAddress(&p_a,   g_a);
    cudaGetSymbolAddress(&p_x2,  g_x2);
    cudaGetSymbolAddress(&p_m,   g_m);
    cudaGetSymbolAddress(&p_wt,  g_wt);
    float* h   = (float*)p_h;
    float* qkv = (float*)p_qkv;
    float* a   = (float*)p_a;
    float* x2  = (float*)p_x2;
    float* mm  = (float*)p_m;
    float* wt  = (float*)p_wt;

    float* wt_attn = wt;                       // 3*E*E
    float* wt_proj = wt + 3 * EMB * EMB;       // E*E
    float* wt_fc   = wt + 4 * EMB * EMB;       // 4*E*E
    float* wt_out  = wt + 8 * EMB * EMB;       // 4*E*E

    cudaFuncSetAttribute(attn_kernel,
                         cudaFuncAttributeMaxDynamicSharedMemorySize,
                         ATTN_SMEM_BYTES);
    cudaFuncSetAttribute(gemm_tf32<0>,
                         cudaFuncAttributeMaxDynamicSharedMemorySize,
                         GEMM_SMEM_BYTES);
    cudaFuncSetAttribute(gemm_tf32<1>,
                         cudaFuncAttributeMaxDynamicSharedMemorySize,
                         GEMM_SMEM_BYTES);
    cudaFuncSetAttribute(gemm_tf32<2>,
                         cudaFuncAttributeMaxDynamicSharedMemorySize,
                         GEMM_SMEM_BYTES);

    // 0. pre-round weights to tf32 values (exact feed for the mma)
    {
        const int n4a = 3 * EMB * EMB / 4;
        const int n4p = EMB * EMB / 4;
        const int n4f = 4 * EMB * EMB / 4;
        round_tf32_kernel<<<(n4a + 255) / 256, 256>>>(w_attn, wt_attn, n4a);
        round_tf32_kernel<<<(n4p + 255) / 256, 256>>>(w_proj, wt_proj, n4p);
        round_tf32_kernel<<<(n4f + 255) / 256, 256>>>(w_fc,   wt_fc,   n4f);
        round_tf32_kernel<<<(n4f + 255) / 256, 256>>>(w_out,  wt_out,  n4f);
    }

    // 1. ln1 (tf32-rounded output)
    ln_kernel<<<NTOK, 256>>>(x, ln1_g, ln1_b, h);
    // 2. qkv = h @ w_attn + b_attn            [4096, 3072]
    gemm_tf32<0><<<dim3(3 * EMB / 128, NTOK / 128), 256, GEMM_SMEM_BYTES>>>(
        NTOK, 3 * EMB, EMB, h, wt_attn, b_attn, nullptr, qkv);
    // 3. attention -> a (merged heads, token layout, tf32-rounded)
    attn_kernel<<<dim3(BATCH * NH, S_LEN / 64), 256, ATTN_SMEM_BYTES>>>(qkv, a);
    // 4. x2 = x + a @ w_proj + b_proj
    gemm_tf32<1><<<dim3(EMB / 128, NTOK / 128), 256, GEMM_SMEM_BYTES>>>(
        NTOK, EMB, EMB, a, wt_proj, b_proj, x, x2);
    // 5. ln2 (tf32-rounded output)
    ln_kernel<<<NTOK, 256>>>(x2, ln2_g, ln2_b, h);
    // 6. m = gelu(h @ w_fc + b_fc)            [4096, 4096], tf32-rounded
    gemm_tf32<2><<<dim3(4 * EMB / 128, NTOK / 128), 256, GEMM_SMEM_BYTES>>>(
        NTOK, 4 * EMB, EMB, h, wt_fc, b_fc, nullptr, mm);
    // 7. out = x2 + m @ w_out + b_out
    gemm_tf32<1><<<dim3(EMB / 128, NTOK / 128), 256, GEMM_SMEM_BYTES>>>(
        NTOK, EMB, 4 * EMB, mm, wt_out, b_out, x2, out);
}

// round 8
// speedup vs baseline: 3.4652x; 1.3778x over previous
#include <cuda_runtime.h>
#include <math.h>
#include <stdint.h>

// ---------------------------------------------------------------------------
// Problem constants
// ---------------------------------------------------------------------------
#define S_LEN 1024
#define BATCH 4
#define EMB   1024
#define NH    16
#define HD    64
#define NTOK  (S_LEN * BATCH)     // 4096 tokens, token index t = s*BATCH + b
#define LN_EPS 1e-5f

// ---------------------------------------------------------------------------
// Scratch (device globals -- allocation-free kernel_launch requirement)
// ---------------------------------------------------------------------------
__device__ float g_h  [NTOK * EMB];          // 16 MB (ln output, tf32-rounded)
__device__ float g_qkv[NTOK * 3 * EMB];      // 48 MB
__device__ float g_a  [NTOK * EMB];          // 16 MB (attn out, tf32-rounded)
__device__ float g_x2 [NTOK * EMB];          // 16 MB
__device__ float g_m  [NTOK * 4 * EMB];      // 64 MB (gelu out, tf32-rounded)
__device__ float g_wt [12 * EMB * EMB];      // 48 MB (tf32-rounded weights)
__device__ float g_vt [NH * BATCH * HD * S_LEN];  // 16 MB (V transposed, tf32)

// ---------------------------------------------------------------------------
// TF32 helpers
// ---------------------------------------------------------------------------
__device__ __forceinline__ uint32_t f2tf32(float x) {
    uint32_t u;
    asm("cvt.rna.tf32.f32 %0, %1;" : "=r"(u) : "f"(x));
    return u;
}
__device__ __forceinline__ float tf32r(float x) {
    return __uint_as_float(f2tf32(x));
}

__device__ __forceinline__ void mma_tf32(
    float c[4], const uint32_t a[4], const uint32_t b[2])
{
    asm volatile(
        "mma.sync.aligned.m16n8k8.row.col.f32.tf32.tf32.f32 "
        "{%0,%1,%2,%3}, {%4,%5,%6,%7}, {%8,%9}, {%0,%1,%2,%3};\n"
        : "+f"(c[0]), "+f"(c[1]), "+f"(c[2]), "+f"(c[3])
        : "r"(a[0]), "r"(a[1]), "r"(a[2]), "r"(a[3]),
          "r"(b[0]), "r"(b[1]));
}

// cp.async helpers
__device__ __forceinline__ void cp_async16(void* smem_ptr, const void* gptr) {
    uint32_t s = (uint32_t)__cvta_generic_to_shared(smem_ptr);
    asm volatile("cp.async.cg.shared.global [%0], [%1], 16;\n"
                 :: "r"(s), "l"(gptr));
}
__device__ __forceinline__ void cp_commit() {
    asm volatile("cp.async.commit_group;\n");
}
template <int N>
__device__ __forceinline__ void cp_wait() {
    asm volatile("cp.async.wait_group %0;\n" :: "n"(N));
}

// ---------------------------------------------------------------------------
// Weight pre-rounding: dst = tf32_round(src), vectorized float4
// ---------------------------------------------------------------------------
__global__ void __launch_bounds__(256) round_tf32_kernel(
    const float* __restrict__ src, float* __restrict__ dst, int n4)
{
    int i = blockIdx.x * 256 + threadIdx.x;
    if (i < n4) {
        float4 v = reinterpret_cast<const float4*>(src)[i];
        v.x = tf32r(v.x); v.y = tf32r(v.y); v.z = tf32r(v.z); v.w = tf32r(v.w);
        reinterpret_cast<float4*>(dst)[i] = v;
    }
}

// ---------------------------------------------------------------------------
// LayerNorm (output tf32-rounded: it only ever feeds GEMM A-operands)
// ---------------------------------------------------------------------------
__global__ void __launch_bounds__(256) ln_kernel(
    const float* __restrict__ x, const float* __restrict__ gamma,
    const float* __restrict__ beta, float* __restrict__ out)
{
    const int row = blockIdx.x;
    const int t   = threadIdx.x;
    const float4* xr = reinterpret_cast<const float4*>(x + (size_t)row * EMB);
    float4 v = xr[t];

    float s  = v.x + v.y + v.z + v.w;
    float sq = v.x * v.x + v.y * v.y + v.z * v.z + v.w * v.w;
    #pragma unroll
    for (int m = 16; m > 0; m >>= 1) {
        s  += __shfl_xor_sync(0xffffffffu, s,  m);
        sq += __shfl_xor_sync(0xffffffffu, sq, m);
    }

    __shared__ float sh_s[8], sh_q[8];
    __shared__ float sh_mean, sh_rstd;
    const int warp = t >> 5, lane = t & 31;
    if (lane == 0) { sh_s[warp] = s; sh_q[warp] = sq; }
    __syncthreads();
    if (t == 0) {
        float ts = 0.f, tq = 0.f;
        #pragma unroll
        for (int i = 0; i < 8; i++) { ts += sh_s[i]; tq += sh_q[i]; }
        float mean = ts * (1.0f / EMB);
        float var  = tq * (1.0f / EMB) - mean * mean;
        sh_mean = mean;
        sh_rstd = rsqrtf(var + LN_EPS);
    }
    __syncthreads();
    const float mean = sh_mean, rstd = sh_rstd;

    float4 g4 = reinterpret_cast<const float4*>(gamma)[t];
    float4 b4 = reinterpret_cast<const float4*>(beta)[t];
    float4 o;
    o.x = tf32r((v.x - mean) * rstd * g4.x + b4.x);
    o.y = tf32r((v.y - mean) * rstd * g4.y + b4.y);
    o.z = tf32r((v.z - mean) * rstd * g4.z + b4.z);
    o.w = tf32r((v.w - mean) * rstd * g4.w + b4.w);
    reinterpret_cast<float4*>(out + (size_t)row * EMB)[t] = o;
}

// ---------------------------------------------------------------------------
// GELU (GPT-2 tanh approximation)
// ---------------------------------------------------------------------------
__device__ __forceinline__ float gelu_f(float x) {
    const float c = 0.7978845608028654f;   // sqrt(2/pi)
    float x3 = x * x * x;
    return 0.5f * x * (1.0f + tanhf(c * (x + 0.044715f * x3)));
}

// ---------------------------------------------------------------------------
// TF32 tensor-core GEMM, cp.async 3-stage pipeline (round-6, proven).
// ---------------------------------------------------------------------------
#define GAST 36
#define GBST 136
#define GA_STG (128 * GAST)               // 4608 u32
#define GB_STG (32 * GBST)                // 4352 u32
#define G_STG  (GA_STG + GB_STG)          // 8960 u32 = 35840 B
#define NSTAGE 3
#define GEMM_SMEM_BYTES (NSTAGE * G_STG * 4)   // 107520 B

template <int EPI>
__global__ void __launch_bounds__(256, 2) gemm_tf32(
    int M, int N, int K,
    const float* __restrict__ A, const float* __restrict__ W,
    const float* __restrict__ bias, const float* __restrict__ res,
    float* __restrict__ C)
{
    extern __shared__ uint32_t smem_u[];

    const int bm = blockIdx.y, bn = blockIdx.x;
    const int t    = threadIdx.x;
    const int warp = t >> 5, lane = t & 31;
    const int wm = warp >> 2;
    const int wn = warp & 3;
    const int g  = lane >> 2;
    const int q  = lane & 3;

    const int arow0 = t >> 3;
    const int ac    = (t & 7) << 2;
    const int brow0 = t >> 5;
    const int bc    = (t & 31) << 2;
    const float* aSrc = A + (size_t)(bm * 128 + arow0) * K + ac;
    const float* bSrc = W + (size_t)brow0 * N + bn * 128 + bc;
    const int aDst = arow0 * GAST + ac;
    const int bDst = brow0 * GBST + bc;

    float acc[4][4][4];
    #pragma unroll
    for (int mi = 0; mi < 4; mi++)
        #pragma unroll
        for (int ni = 0; ni < 4; ni++)
            #pragma unroll
            for (int j = 0; j < 4; j++) acc[mi][ni][j] = 0.f;

    #define ISSUE(stg, kt)                                                     \
        {                                                                      \
            uint32_t* as = smem_u + (stg) * G_STG;                             \
            uint32_t* bs = as + GA_STG;                                        \
            _Pragma("unroll")                                                  \
            for (int i = 0; i < 4; i++)                                        \
                cp_async16(as + aDst + i * (32 * GAST),                        \
                           aSrc + (size_t)(kt) * 32 + (size_t)i * 32 * K);     \
            _Pragma("unroll")                                                  \
            for (int i = 0; i < 4; i++)                                        \
                cp_async16(bs + bDst + i * (8 * GBST),                         \
                           bSrc + ((size_t)(kt) * 32 + i * 8) * N);            \
        }

    const int ntiles = K / 32;
    ISSUE(0, 0); cp_commit();
    ISSUE(1, 1); cp_commit();

    int buf = 0;
    for (int kt = 0; kt < ntiles; kt++) {
        cp_wait<1>();
        __syncthreads();

        if (kt + 2 < ntiles) {
            int nstg = buf + 2; if (nstg >= NSTAGE) nstg -= NSTAGE;
            ISSUE(nstg, kt + 2);
        }
        cp_commit();

        {
            const uint32_t* as = smem_u + buf * G_STG + (wm * 64 + g) * GAST;
            const uint32_t* bs = smem_u + buf * G_STG + GA_STG + wn * 32 + g;
            #pragma unroll
            for (int ks = 0; ks < 4; ks++) {
                const int kk = ks * 8;
                uint32_t af[4][4], bf[4][2];
                #pragma unroll
                for (int mi = 0; mi < 4; mi++) {
                    const uint32_t* p = as + mi * 16 * GAST + kk + q;
                    af[mi][0] = p[0];
                    af[mi][1] = p[8 * GAST];
                    af[mi][2] = p[4];
                    af[mi][3] = p[8 * GAST + 4];
                }
                #pragma unroll
                for (int ni = 0; ni < 4; ni++) {
                    const uint32_t* p = bs + (kk + q) * GBST + ni * 8;
                    bf[ni][0] = p[0];
                    bf[ni][1] = p[4 * GBST];
                }
                #pragma unroll
                for (int mi = 0; mi < 4; mi++)
                    #pragma unroll
                    for (int ni = 0; ni < 4; ni++)
                        mma_tf32(acc[mi][ni], af[mi], bf[ni]);
            }
        }

        buf++; if (buf == NSTAGE) buf = 0;
    }
    #undef ISSUE

    const int row_base = bm * 128 + wm * 64;
    const int col_base = bn * 128 + wn * 32;
    #pragma unroll
    for (int mi = 0; mi < 4; mi++) {
        #pragma unroll
        for (int ni = 0; ni < 4; ni++) {
            const int col = col_base + ni * 8 + 2 * q;
            const float b0 = bias[col], b1 = bias[col + 1];
            #pragma unroll
            for (int half = 0; half < 2; half++) {
                const int row = row_base + mi * 16 + g + half * 8;
                const size_t base = (size_t)row * N + col;
                float v0 = acc[mi][ni][half * 2 + 0] + b0;
                float v1 = acc[mi][ni][half * 2 + 1] + b1;
                if (EPI == 1) { v0 += res[base]; v1 += res[base + 1]; }
                if (EPI == 2) {
                    v0 = tf32r(gelu_f(v0));
                    v1 = tf32r(gelu_f(v1));
                }
                *reinterpret_cast<float2*>(C + base) = make_float2(v0, v1);
            }
        }
    }
}

// ---------------------------------------------------------------------------
// V transpose: qkv V slice -> vt[bh][d][s], tf32-rounded.
// grid (64 bh, 32 s-tiles, 2 d-tiles), block (32, 8).
// ---------------------------------------------------------------------------
__global__ void __launch_bounds__(256) vtrans_kernel(
    const float* __restrict__ qkv, float* __restrict__ vt)
{
    __shared__ float tile[32][33];
    const int bh = blockIdx.x, b = bh >> 4, h = bh & 15;
    const int s0 = blockIdx.y * 32, d0 = blockIdx.z * 32;
    const int tx = threadIdx.x, ty = threadIdx.y;

    #pragma unroll
    for (int i = 0; i < 4; i++) {
        int s = s0 + ty * 4 + i;
        tile[ty * 4 + i][tx] =
            qkv[((size_t)s * BATCH + b) * (3 * EMB) + 2 * EMB + h * HD + d0 + tx];
    }
    __syncthreads();
    #pragma unroll
    for (int i = 0; i < 4; i++) {
        int d = d0 + ty * 4 + i;
        vt[((size_t)bh * HD + d) * S_LEN + s0 + tx] = tf32r(tile[tx][ty * 4 + i]);
    }
}

// ---------------------------------------------------------------------------
// Flash attention on tensor cores (tf32 m16n8k8), online softmax.
// Block = (b,h) x 64-row q tile; 4 warps, each owns 16 q rows.
// Q lives in registers as tf32 fragments for the whole KV loop.
// K tile smem [64][68] (conflict-free fragment reads: banks 4g+q).
// V read pre-transposed from g_vt -> Vts[d][kv] [64][68].
// P re-laid out via per-warp Ps [16][68] (tf32-rounded).
// ---------------------------------------------------------------------------
#define ATS 68
#define ATTN_SMEM_BYTES (3 * 64 * ATS * 4)   // 52224

__global__ void __launch_bounds__(128) attn_mma_kernel(
    const float* __restrict__ qkv, const float* __restrict__ vt,
    float* __restrict__ out)
{
    extern __shared__ float sm[];
    float* Ks  = sm;                  // [64][ATS]; doubles as Q staging
    float* Vts = sm + 64 * ATS;       // [64][ATS]
    float* Ps  = sm + 2 * 64 * ATS;   // [64][ATS]

    const int bh = blockIdx.x, b = bh >> 4, h = bh & 15;
    const int q0 = blockIdx.y * 64;
    const int t = threadIdx.x, w = t >> 5, lane = t & 31;
    const int g = lane >> 2, q = lane & 3;
    const int wrow = w * 16;

    // ---- stage Q (coalesced), then build register fragments ----
    #pragma unroll
    for (int i = 0; i < 8; i++) {
        int idx = t + i * 128;
        int r = idx >> 4, c = (idx & 15) << 2;
        float4 v = *reinterpret_cast<const float4*>(
            qkv + ((size_t)(q0 + r) * BATCH + b) * (3 * EMB) + h * HD + c);
        v.x = tf32r(v.x); v.y = tf32r(v.y); v.z = tf32r(v.z); v.w = tf32r(v.w);
        *reinterpret_cast<float4*>(&Ks[r * ATS + c]) = v;
    }
    __syncthreads();

    uint32_t qf[8][4];
    #pragma unroll
    for (int kt = 0; kt < 8; kt++) {
        qf[kt][0] = __float_as_uint(Ks[(wrow + g)     * ATS + kt * 8 + q]);
        qf[kt][1] = __float_as_uint(Ks[(wrow + g + 8) * ATS + kt * 8 + q]);
        qf[kt][2] = __float_as_uint(Ks[(wrow + g)     * ATS + kt * 8 + q + 4]);
        qf[kt][3] = __float_as_uint(Ks[(wrow + g + 8) * ATS + kt * 8 + q + 4]);
    }
    __syncthreads();

    float o[8][4];
    #pragma unroll
    for (int nt = 0; nt < 8; nt++)
        #pragma unroll
        for (int j = 0; j < 4; j++) o[nt][j] = 0.f;
    float m0 = -1e30f, m1 = -1e30f, l0 = 0.f, l1 = 0.f;

    for (int kv0 = 0; kv0 < S_LEN; kv0 += 64) {
        // ---- load K tile (tf32-rounded) and Vt tile (pre-rounded) ----
        #pragma unroll
        for (int i = 0; i < 8; i++) {
            int idx = t + i * 128;
            int r = idx >> 4, c = (idx & 15) << 2;
            float4 kv4 = *reinterpret_cast<const float4*>(
                qkv + ((size_t)(kv0 + r) * BATCH + b) * (3 * EMB) + EMB + h * HD + c);
            kv4.x = tf32r(kv4.x); kv4.y = tf32r(kv4.y);
            kv4.z = tf32r(kv4.z); kv4.w = tf32r(kv4.w);
            *reinterpret_cast<float4*>(&Ks[r * ATS + c]) = kv4;
            float4 vv4 = *reinterpret_cast<const float4*>(
                vt + ((size_t)bh * HD + r) * S_LEN + kv0 + c);
            *reinterpret_cast<float4*>(&Vts[r * ATS + c]) = vv4;
        }
        __syncthreads();

        // ---- scores: warp computes 16 x 64 via 8x8 mmas ----
        float sc[8][4];
        #pragma unroll
        for (int nt = 0; nt < 8; nt++) {
            sc[nt][0] = sc[nt][1] = sc[nt][2] = sc[nt][3] = 0.f;
            #pragma unroll
            for (int kt = 0; kt < 8; kt++) {
                uint32_t bfr[2];
                bfr[0] = __float_as_uint(Ks[(nt * 8 + g) * ATS + kt * 8 + q]);
                bfr[1] = __float_as_uint(Ks[(nt * 8 + g) * ATS + kt * 8 + q + 4]);
                mma_tf32(sc[nt], qf[kt], bfr);
            }
        }

        // ---- online softmax (rows g and g+8; quad shfl covers 64 cols) ----
        float mx0 = -1e30f, mx1 = -1e30f;
        #pragma unroll
        for (int nt = 0; nt < 8; nt++) {
            sc[nt][0] *= 0.125f; sc[nt][1] *= 0.125f;
            sc[nt][2] *= 0.125f; sc[nt][3] *= 0.125f;
            mx0 = fmaxf(mx0, fmaxf(sc[nt][0], sc[nt][1]));
            mx1 = fmaxf(mx1, fmaxf(sc[nt][2], sc[nt][3]));
        }
        mx0 = fmaxf(mx0, __shfl_xor_sync(0xffffffffu, mx0, 1));
        mx0 = fmaxf(mx0, __shfl_xor_sync(0xffffffffu, mx0, 2));
        mx1 = fmaxf(mx1, __shfl_xor_sync(0xffffffffu, mx1, 1));
        mx1 = fmaxf(mx1, __shfl_xor_sync(0xffffffffu, mx1, 2));

        const float mn0 = fmaxf(m0, mx0), mn1 = fmaxf(m1, mx1);
        const float a0 = __expf(m0 - mn0), a1 = __expf(m1 - mn1);
        float s0 = 0.f, s1 = 0.f;
        #pragma unroll
        for (int nt = 0; nt < 8; nt++) {
            float p0 = __expf(sc[nt][0] - mn0);
            float p1 = __expf(sc[nt][1] - mn0);
            float p2 = __expf(sc[nt][2] - mn1);
            float p3 = __expf(sc[nt][3] - mn1);
            s0 += p0 + p1; s1 += p2 + p3;
            *reinterpret_cast<float2*>(&Ps[(wrow + g) * ATS + nt * 8 + 2 * q]) =
                make_float2(tf32r(p0), tf32r(p1));
            *reinterpret_cast<float2*>(&Ps[(wrow + g + 8) * ATS + nt * 8 + 2 * q]) =
                make_float2(tf32r(p2), tf32r(p3));
        }
        s0 += __shfl_xor_sync(0xffffffffu, s0, 1);
        s0 += __shfl_xor_sync(0xffffffffu, s0, 2);
        s1 += __shfl_xor_sync(0xffffffffu, s1, 1);
        s1 += __shfl_xor_sync(0xffffffffu, s1, 2);

        l0 = l0 * a0 + s0; l1 = l1 * a1 + s1;
        m0 = mn0; m1 = mn1;
        #pragma unroll
        for (int nt = 0; nt < 8; nt++) {
            o[nt][0] *= a0; o[nt][1] *= a0;
            o[nt][2] *= a1; o[nt][3] *= a1;
        }
        __syncwarp();   // Ps written+read within this warp

        // ---- PV: O[16][64] += P[16][64] @ V[64][64] ----
        #pragma unroll
        for (int kt = 0; kt < 8; kt++) {
            uint32_t af[4];
            af[0] = __float_as_uint(Ps[(wrow + g)     * ATS + kt * 8 + q]);
            af[1] = __float_as_uint(Ps[(wrow + g + 8) * ATS + kt * 8 + q]);
            af[2] = __float_as_uint(Ps[(wrow + g)     * ATS + kt * 8 + q + 4]);
            af[3] = __float_as_uint(Ps[(wrow + g + 8) * ATS + kt * 8 + q + 4]);
            #pragma unroll
            for (int nt = 0; nt < 8; nt++) {
                uint32_t bfr[2];
                bfr[0] = __float_as_uint(Vts[(nt * 8 + g) * ATS + kt * 8 + q]);
                bfr[1] = __float_as_uint(Vts[(nt * 8 + g) * ATS + kt * 8 + q + 4]);
                mma_tf32(o[nt], af, bfr);
            }
        }
        __syncthreads();   // protect Ks/Vts before next iteration overwrites
    }

    // ---- finalize: divide by l, tf32-round (feeds proj GEMM), store ----
    const float inv0 = 1.0f / l0, inv1 = 1.0f / l1;
    const int s_row0 = q0 + wrow + g;
    #pragma unroll
    for (int nt = 0; nt < 8; nt++) {
        const int col = h * HD + nt * 8 + 2 * q;
        *reinterpret_cast<float2*>(
            out + ((size_t)s_row0 * BATCH + b) * EMB + col) =
            make_float2(tf32r(o[nt][0] * inv0), tf32r(o[nt][1] * inv0));
        *reinterpret_cast<float2*>(
            out + ((size_t)(s_row0 + 8) * BATCH + b) * EMB + col) =
            make_float2(tf32r(o[nt][2] * inv1), tf32r(o[nt][3] * inv1));
    }
}

// ---------------------------------------------------------------------------
// Launch
// ---------------------------------------------------------------------------
extern "C" void kernel_launch(void* const* d_in, const int* in_sizes, int n_in,
                              void* d_out, int out_size)
{
    const float* x      = (const float*)d_in[0];
    const float* ln1_g  = (const float*)d_in[1];
    const float* ln1_b  = (const float*)d_in[2];
    const float* w_attn = (const float*)d_in[3];
    const float* b_attn = (const float*)d_in[4];
    const float* w_proj = (const float*)d_in[5];
    const float* b_proj = (const float*)d_in[6];
    const float* ln2_g  = (const float*)d_in[7];
    const float* ln2_b  = (const float*)d_in[8];
    const float* w_fc   = (const float*)d_in[9];
    const float* b_fc   = (const float*)d_in[10];
    const float* w_out  = (const float*)d_in[11];
    const float* b_out  = (const float*)d_in[12];
    float* out = (float*)d_out;

    void *p_h, *p_qkv, *p_a, *p_x2, *p_m, *p_wt, *p_vt;
    cudaGetSymbolAddress(&p_h,   g_h);
    cudaGetSymbolAddress(&p_qkv, g_qkv);
    cudaGetSymbolAddress(&p_a,   g_a);
    cudaGetSymbolAddress(&p_x2,  g_x2);
    cudaGetSymbolAddress(&p_m,   g_m);
    cudaGetSymbolAddress(&p_wt,  g_wt);
    cudaGetSymbolAddress(&p_vt,  g_vt);
    float* h   = (float*)p_h;
    float* qkv = (float*)p_qkv;
    float* a   = (float*)p_a;
    float* x2  = (float*)p_x2;
    float* mm  = (float*)p_m;
    float* wt  = (float*)p_wt;
    float* vt  = (float*)p_vt;

    float* wt_attn = wt;
    float* wt_proj = wt + 3 * EMB * EMB;
    float* wt_fc   = wt + 4 * EMB * EMB;
    float* wt_out  = wt + 8 * EMB * EMB;

    cudaFuncSetAttribute(attn_mma_kernel,
                         cudaFuncAttributeMaxDynamicSharedMemorySize,
                         ATTN_SMEM_BYTES);
    cudaFuncSetAttribute(gemm_tf32<0>,
                         cudaFuncAttributeMaxDynamicSharedMemorySize,
                         GEMM_SMEM_BYTES);
    cudaFuncSetAttribute(gemm_tf32<1>,
                         cudaFuncAttributeMaxDynamicSharedMemorySize,
                         GEMM_SMEM_BYTES);
    cudaFuncSetAttribute(gemm_tf32<2>,
                         cudaFuncAttributeMaxDynamicSharedMemorySize,
                         GEMM_SMEM_BYTES);

    // 0. pre-round weights to tf32 values (exact feed for the mma)
    {
        const int n4a = 3 * EMB * EMB / 4;
        const int n4p = EMB * EMB / 4;
        const int n4f = 4 * EMB * EMB / 4;
        round_tf32_kernel<<<(n4a + 255) / 256, 256>>>(w_attn, wt_attn, n4a);
        round_tf32_kernel<<<(n4p + 255) / 256, 256>>>(w_proj, wt_proj, n4p);
        round_tf32_kernel<<<(n4f + 255) / 256, 256>>>(w_fc,   wt_fc,   n4f);
        round_tf32_kernel<<<(n4f + 255) / 256, 256>>>(w_out,  wt_out,  n4f);
    }

    // 1. ln1 (tf32-rounded output)
    ln_kernel<<<NTOK, 256>>>(x, ln1_g, ln1_b, h);
    // 2. qkv = h @ w_attn + b_attn            [4096, 3072]
    gemm_tf32<0><<<dim3(3 * EMB / 128, NTOK / 128), 256, GEMM_SMEM_BYTES>>>(
        NTOK, 3 * EMB, EMB, h, wt_attn, b_attn, nullptr, qkv);
    // 3a. V transpose for tensor-core PV
    vtrans_kernel<<<dim3(NH * BATCH, S_LEN / 32, HD / 32), dim3(32, 8)>>>(qkv, vt);
    // 3b. attention -> a (merged heads, token layout, tf32-rounded)
    attn_mma_kernel<<<dim3(BATCH * NH, S_LEN / 64), 128, ATTN_SMEM_BYTES>>>(
        qkv, vt, a);
    // 4. x2 = x + a @ w_proj + b_proj
    gemm_tf32<1><<<dim3(EMB / 128, NTOK / 128), 256, GEMM_SMEM_BYTES>>>(
        NTOK, EMB, EMB, a, wt_proj, b_proj, x, x2);
    // 5. ln2 (tf32-rounded output)
    ln_kernel<<<NTOK, 256>>>(x2, ln2_g, ln2_b, h);
    // 6. m = gelu(h @ w_fc + b_fc)            [4096, 4096], tf32-rounded
    gemm_tf32<2><<<dim3(4 * EMB / 128, NTOK / 128), 256, GEMM_SMEM_BYTES>>>(
        NTOK, 4 * EMB, EMB, h, wt_fc, b_fc, nullptr, mm);
    // 7. out = x2 + m @ w_out + b_out
    gemm_tf32<1><<<dim3(EMB / 128, NTOK / 128), 256, GEMM_SMEM_BYTES>>>(
        NTOK, EMB, 4 * EMB, mm, wt_out, b_out, x2, out);
}